// round 1
// baseline (speedup 1.0000x reference)
#include <cuda_runtime.h>
#include <math.h>

#define Bc 4
#define Sc 1024
#define DIMc 1024
#define Hc 16
#define DHc 64
#define Mc (Bc * Sc)

// Scratch (allocation-free rule: __device__ globals)
__device__ float g_q[Mc * DIMc];
__device__ float g_k[Mc * DIMc];
__device__ float g_v[Mc * DIMc];
__device__ float g_o[Mc * DIMc];

// ----------------------------------------------------------------------------
// SGEMM: C[m][n] = sum_k A[m][k] * W[n][k] + bias[n]
// A: (M x K) row-major, W: (N x K) row-major (eqx Linear weight), 128x128x8 tiles
// ----------------------------------------------------------------------------
__global__ void __launch_bounds__(256) sgemm_bias(
    const float* __restrict__ A, const float* __restrict__ W,
    const float* __restrict__ bias, float* __restrict__ C, int K, int N) {
  __shared__ float As[8][132];
  __shared__ float Bs[8][132];
  const int tid = threadIdx.x;
  const int tx = tid & 15, ty = tid >> 4;
  const int row0 = blockIdx.y * 128, col0 = blockIdx.x * 128;
  const float* Ab = A + (size_t)row0 * K;
  const float* Wb = W + (size_t)col0 * K;
  const int lr = tid >> 1, lc = (tid & 1) * 4;

  float acc[8][8];
#pragma unroll
  for (int i = 0; i < 8; i++)
#pragma unroll
    for (int j = 0; j < 8; j++) acc[i][j] = 0.f;

  for (int k0 = 0; k0 < K; k0 += 8) {
    float4 a4 = *(const float4*)(Ab + (size_t)lr * K + k0 + lc);
    float4 b4 = *(const float4*)(Wb + (size_t)lr * K + k0 + lc);
    As[lc + 0][lr] = a4.x; As[lc + 1][lr] = a4.y;
    As[lc + 2][lr] = a4.z; As[lc + 3][lr] = a4.w;
    Bs[lc + 0][lr] = b4.x; Bs[lc + 1][lr] = b4.y;
    Bs[lc + 2][lr] = b4.z; Bs[lc + 3][lr] = b4.w;
    __syncthreads();
#pragma unroll
    for (int k = 0; k < 8; k++) {
      float4 a0 = *(const float4*)&As[k][ty * 4];
      float4 a1 = *(const float4*)&As[k][64 + ty * 4];
      float4 b0 = *(const float4*)&Bs[k][tx * 4];
      float4 b1 = *(const float4*)&Bs[k][64 + tx * 4];
      float ar[8] = {a0.x, a0.y, a0.z, a0.w, a1.x, a1.y, a1.z, a1.w};
      float br[8] = {b0.x, b0.y, b0.z, b0.w, b1.x, b1.y, b1.z, b1.w};
#pragma unroll
      for (int i = 0; i < 8; i++)
#pragma unroll
        for (int j = 0; j < 8; j++) acc[i][j] = fmaf(ar[i], br[j], acc[i][j]);
    }
    __syncthreads();
  }

#pragma unroll
  for (int i = 0; i < 8; i++) {
    int r = row0 + ((i < 4) ? (ty * 4 + i) : (64 + ty * 4 + (i - 4)));
#pragma unroll
    for (int jh = 0; jh < 2; jh++) {
      int c = col0 + jh * 64 + tx * 4;
      float4 o;
      o.x = acc[i][jh * 4 + 0] + bias[c + 0];
      o.y = acc[i][jh * 4 + 1] + bias[c + 1];
      o.z = acc[i][jh * 4 + 2] + bias[c + 2];
      o.w = acc[i][jh * 4 + 3] + bias[c + 3];
      *(float4*)(C + (size_t)r * N + c) = o;
    }
  }
}

// ----------------------------------------------------------------------------
// RoPE (GPT-NeoX half-split), in place on q and k. Angles in double => exact.
// ----------------------------------------------------------------------------
__global__ void rope_kernel(float* __restrict__ q, float* __restrict__ k) {
  int idx = blockIdx.x * blockDim.x + threadIdx.x;
  if (idx >= Mc * Hc * 32) return;
  int j = idx & 31;
  int h = (idx >> 5) & (Hc - 1);
  int m = idx >> 9;            // 0..4095 (b*S+s)
  int s = m & (Sc - 1);
  double freq = exp(-(double)j * (log(10000.0) / 32.0));  // theta^{-2j/64}
  double ang = (double)s * freq;
  float cs = (float)cos(ang), sn = (float)sin(ang);
  size_t base = (size_t)m * DIMc + h * DHc;
  float q1 = q[base + j], q2 = q[base + j + 32];
  q[base + j]      = q1 * cs - q2 * sn;
  q[base + j + 32] = q2 * cs + q1 * sn;
  float k1 = k[base + j], k2 = k[base + j + 32];
  k[base + j]      = k1 * cs - k2 * sn;
  k[base + j + 32] = k2 * cs + k1 * sn;
}

// ----------------------------------------------------------------------------
// Flash attention fp32: 64 q-rows per block, 64-col kv tiles, online softmax.
// q,k,v,o in (B,S,H,DH) row-major layout. 256 threads = 16x16, 4x4 microtiles.
// ----------------------------------------------------------------------------
#define FPAD 68
__global__ void __launch_bounds__(256) flash_kernel(
    const float* __restrict__ q, const float* __restrict__ k,
    const float* __restrict__ v, float* __restrict__ o) {
  extern __shared__ float sm[];
  float* Qs = sm;                  // [d][i], 64 x FPAD
  float* Ks = Qs + 64 * FPAD;      // [d][j]
  float* Vs = Ks + 64 * FPAD;      // [j][d]
  float* Ps = Vs + 64 * FPAD;      // [j][i]

  const int tid = threadIdx.x;
  const int tx = tid & 15, ty = tid >> 4;
  const int bh = blockIdx.y;
  const int b = bh >> 4, h = bh & 15;
  const int q0 = blockIdx.x * 64;
  const float* qb = q + (size_t)b * Sc * DIMc + h * DHc;
  const float* kb = k + (size_t)b * Sc * DIMc + h * DHc;
  const float* vb = v + (size_t)b * Sc * DIMc + h * DHc;

  // Load Q tile, transposed into Qs[d][i]
  for (int idx = tid; idx < 64 * 16; idx += 256) {
    int i = idx >> 4, d4 = (idx & 15) * 4;
    float4 t4 = *(const float4*)(qb + (size_t)(q0 + i) * DIMc + d4);
    Qs[(d4 + 0) * FPAD + i] = t4.x;
    Qs[(d4 + 1) * FPAD + i] = t4.y;
    Qs[(d4 + 2) * FPAD + i] = t4.z;
    Qs[(d4 + 3) * FPAD + i] = t4.w;
  }

  float m_i[4], l_i[4], acc[4][4];
#pragma unroll
  for (int r = 0; r < 4; r++) {
    m_i[r] = -INFINITY;
    l_i[r] = 0.f;
#pragma unroll
    for (int c = 0; c < 4; c++) acc[r][c] = 0.f;
  }

  const float scale = 0.125f;  // 1/sqrt(64)

  for (int t = 0; t < 16; t++) {
    int kv0 = t * 64;
    __syncthreads();  // protect Ks/Vs/Ps from previous iteration readers
    for (int idx = tid; idx < 64 * 16; idx += 256) {
      int j = idx >> 4, d4 = (idx & 15) * 4;
      float4 t4 = *(const float4*)(kb + (size_t)(kv0 + j) * DIMc + d4);
      Ks[(d4 + 0) * FPAD + j] = t4.x;
      Ks[(d4 + 1) * FPAD + j] = t4.y;
      Ks[(d4 + 2) * FPAD + j] = t4.z;
      Ks[(d4 + 3) * FPAD + j] = t4.w;
      float4 v4 = *(const float4*)(vb + (size_t)(kv0 + j) * DIMc + d4);
      *(float4*)(Vs + j * FPAD + d4) = v4;
    }
    __syncthreads();

    // S = Q K^T (64x64x64)
    float s[4][4];
#pragma unroll
    for (int r = 0; r < 4; r++)
#pragma unroll
      for (int c = 0; c < 4; c++) s[r][c] = 0.f;
#pragma unroll 16
    for (int d = 0; d < 64; d++) {
      float4 a = *(const float4*)&Qs[d * FPAD + ty * 4];
      float4 bb = *(const float4*)&Ks[d * FPAD + tx * 4];
      float ar[4] = {a.x, a.y, a.z, a.w};
      float br[4] = {bb.x, bb.y, bb.z, bb.w};
#pragma unroll
      for (int r = 0; r < 4; r++)
#pragma unroll
        for (int c = 0; c < 4; c++) s[r][c] = fmaf(ar[r], br[c], s[r][c]);
    }

    // Online softmax per row; row group = 16 lanes (aligned), xor-shuffle reduce
#pragma unroll
    for (int r = 0; r < 4; r++) {
#pragma unroll
      for (int c = 0; c < 4; c++) s[r][c] *= scale;
      float mx = fmaxf(fmaxf(s[r][0], s[r][1]), fmaxf(s[r][2], s[r][3]));
#pragma unroll
      for (int off = 8; off > 0; off >>= 1)
        mx = fmaxf(mx, __shfl_xor_sync(0xffffffffu, mx, off));
      float mn = fmaxf(m_i[r], mx);
      float corr = __expf(m_i[r] - mn);
      float rs = 0.f;
#pragma unroll
      for (int c = 0; c < 4; c++) {
        float p = __expf(s[r][c] - mn);
        rs += p;
        Ps[(tx * 4 + c) * FPAD + ty * 4 + r] = p;
      }
#pragma unroll
      for (int off = 8; off > 0; off >>= 1)
        rs += __shfl_xor_sync(0xffffffffu, rs, off);
      l_i[r] = l_i[r] * corr + rs;
      m_i[r] = mn;
#pragma unroll
      for (int c = 0; c < 4; c++) acc[r][c] *= corr;
    }
    __syncthreads();

    // O += P V (64x64x64)
#pragma unroll 16
    for (int j = 0; j < 64; j++) {
      float4 a = *(const float4*)&Ps[j * FPAD + ty * 4];
      float4 bv = *(const float4*)&Vs[j * FPAD + tx * 4];
      float ar[4] = {a.x, a.y, a.z, a.w};
      float br[4] = {bv.x, bv.y, bv.z, bv.w};
#pragma unroll
      for (int r = 0; r < 4; r++)
#pragma unroll
        for (int c = 0; c < 4; c++) acc[r][c] = fmaf(ar[r], br[c], acc[r][c]);
    }
  }

  // Writeback o[b, q0+row, h, :]
#pragma unroll
  for (int r = 0; r < 4; r++) {
    float inv = 1.f / l_i[r];
    float4 ov = make_float4(acc[r][0] * inv, acc[r][1] * inv,
                            acc[r][2] * inv, acc[r][3] * inv);
    *(float4*)(o + (size_t)(b * Sc + q0 + ty * 4 + r) * DIMc + h * DHc +
               tx * 4) = ov;
  }
}

// ----------------------------------------------------------------------------
extern "C" void kernel_launch(void* const* d_in, const int* in_sizes, int n_in,
                              void* d_out, int out_size) {
  const float* x  = (const float*)d_in[0];
  const float* Wq = (const float*)d_in[1];
  const float* bq = (const float*)d_in[2];
  const float* Wk = (const float*)d_in[3];
  const float* bk = (const float*)d_in[4];
  const float* Wv = (const float*)d_in[5];
  const float* bv = (const float*)d_in[6];
  const float* Wo = (const float*)d_in[7];
  const float* bo = (const float*)d_in[8];
  float* out = (float*)d_out;

  float *qp, *kp, *vp, *op;
  cudaGetSymbolAddress((void**)&qp, g_q);
  cudaGetSymbolAddress((void**)&kp, g_k);
  cudaGetSymbolAddress((void**)&vp, g_v);
  cudaGetSymbolAddress((void**)&op, g_o);

  dim3 gg(DIMc / 128, Mc / 128);  // (8, 32)
  sgemm_bias<<<gg, 256>>>(x, Wq, bq, qp, DIMc, DIMc);
  sgemm_bias<<<gg, 256>>>(x, Wk, bk, kp, DIMc, DIMc);
  sgemm_bias<<<gg, 256>>>(x, Wv, bv, vp, DIMc, DIMc);

  int total = Mc * Hc * 32;
  rope_kernel<<<(total + 255) / 256, 256>>>(qp, kp);

  size_t shm = 4 * 64 * FPAD * sizeof(float);  // 69632 B
  cudaFuncSetAttribute(flash_kernel, cudaFuncAttributeMaxDynamicSharedMemorySize,
                       (int)shm);
  flash_kernel<<<dim3(Sc / 64, Bc * Hc), 256, shm>>>(qp, kp, vp, op);

  sgemm_bias<<<gg, 256>>>(op, Wo, bo, out, DIMc, DIMc);
}

// round 2
// speedup vs baseline: 2.0349x; 2.0349x over previous
#include <cuda_runtime.h>
#include <math.h>

#define Bc 4
#define Sc 1024
#define DIMc 1024
#define Hc 16
#define DHc 64
#define Mc (Bc * Sc)

// Scratch (allocation-free rule: __device__ globals)
__device__ float g_q[Mc * DIMc];
__device__ float g_k[Mc * DIMc];
__device__ float g_v[Mc * DIMc];
__device__ float g_o[Mc * DIMc];
__device__ float g_cs[Sc * 32];
__device__ float g_sn[Sc * 32];

// ----------------------------------------------------------------------------
// SGEMM: C[m][n] = sum_k A[m][k] * W[n][k] + bias[n]
// A: (M x K) row-major, W: (N x K) row-major. 128x128x8 tiles, 256 threads.
// ----------------------------------------------------------------------------
__device__ __forceinline__ void sgemm_body(
    const float* __restrict__ A, const float* __restrict__ W,
    const float* __restrict__ bias, float* __restrict__ C, int K, int N) {
  __shared__ float As[8][132];
  __shared__ float Bs[8][132];
  const int tid = threadIdx.x;
  const int tx = tid & 15, ty = tid >> 4;
  const int row0 = blockIdx.y * 128, col0 = blockIdx.x * 128;
  const float* Ab = A + (size_t)row0 * K;
  const float* Wb = W + (size_t)col0 * K;
  const int lr = tid >> 1, lc = (tid & 1) * 4;

  float acc[8][8];
#pragma unroll
  for (int i = 0; i < 8; i++)
#pragma unroll
    for (int j = 0; j < 8; j++) acc[i][j] = 0.f;

  for (int k0 = 0; k0 < K; k0 += 8) {
    float4 a4 = *(const float4*)(Ab + (size_t)lr * K + k0 + lc);
    float4 b4 = *(const float4*)(Wb + (size_t)lr * K + k0 + lc);
    As[lc + 0][lr] = a4.x; As[lc + 1][lr] = a4.y;
    As[lc + 2][lr] = a4.z; As[lc + 3][lr] = a4.w;
    Bs[lc + 0][lr] = b4.x; Bs[lc + 1][lr] = b4.y;
    Bs[lc + 2][lr] = b4.z; Bs[lc + 3][lr] = b4.w;
    __syncthreads();
#pragma unroll
    for (int k = 0; k < 8; k++) {
      float4 a0 = *(const float4*)&As[k][ty * 4];
      float4 a1 = *(const float4*)&As[k][64 + ty * 4];
      float4 b0 = *(const float4*)&Bs[k][tx * 4];
      float4 b1 = *(const float4*)&Bs[k][64 + tx * 4];
      float ar[8] = {a0.x, a0.y, a0.z, a0.w, a1.x, a1.y, a1.z, a1.w};
      float br[8] = {b0.x, b0.y, b0.z, b0.w, b1.x, b1.y, b1.z, b1.w};
#pragma unroll
      for (int i = 0; i < 8; i++)
#pragma unroll
        for (int j = 0; j < 8; j++) acc[i][j] = fmaf(ar[i], br[j], acc[i][j]);
    }
    __syncthreads();
  }

#pragma unroll
  for (int i = 0; i < 8; i++) {
    int r = row0 + ((i < 4) ? (ty * 4 + i) : (64 + ty * 4 + (i - 4)));
#pragma unroll
    for (int jh = 0; jh < 2; jh++) {
      int c = col0 + jh * 64 + tx * 4;
      float4 o;
      o.x = acc[i][jh * 4 + 0] + bias[c + 0];
      o.y = acc[i][jh * 4 + 1] + bias[c + 1];
      o.z = acc[i][jh * 4 + 2] + bias[c + 2];
      o.w = acc[i][jh * 4 + 3] + bias[c + 3];
      *(float4*)(C + (size_t)r * N + c) = o;
    }
  }
}

__global__ void __launch_bounds__(256) sgemm_bias(
    const float* __restrict__ A, const float* __restrict__ W,
    const float* __restrict__ bias, float* __restrict__ C, int K, int N) {
  sgemm_body(A, W, bias, C, K, N);
}

// Fused QKV: one launch, gridDim.z selects {Wq,Wk,Wv}. Better chip fill + x L2 reuse.
__global__ void __launch_bounds__(256) sgemm_bias_qkv(
    const float* __restrict__ A,
    const float* __restrict__ Wq, const float* __restrict__ bq, float* __restrict__ Cq,
    const float* __restrict__ Wk, const float* __restrict__ bk, float* __restrict__ Ck,
    const float* __restrict__ Wv, const float* __restrict__ bv, float* __restrict__ Cv,
    int K, int N) {
  const float* W; const float* bias; float* C;
  if (blockIdx.z == 0)      { W = Wq; bias = bq; C = Cq; }
  else if (blockIdx.z == 1) { W = Wk; bias = bk; C = Ck; }
  else                      { W = Wv; bias = bv; C = Cv; }
  sgemm_body(A, W, bias, C, K, N);
}

// ----------------------------------------------------------------------------
// RoPE: table of cos/sin (S x 32), computed once in double (exact), then a
// memory-bound fp32 apply pass.
// ----------------------------------------------------------------------------
__global__ void rope_table_kernel() {
  int idx = blockIdx.x * blockDim.x + threadIdx.x;
  if (idx >= Sc * 32) return;
  int j = idx & 31;
  int s = idx >> 5;
  double freq = exp(-(double)j * (log(10000.0) / 32.0));  // theta^{-2j/64}
  double ang = (double)s * freq;
  g_cs[idx] = (float)cos(ang);
  g_sn[idx] = (float)sin(ang);
}

__global__ void __launch_bounds__(256) rope_apply_kernel(float* __restrict__ q,
                                                         float* __restrict__ k) {
  int idx = blockIdx.x * blockDim.x + threadIdx.x;
  if (idx >= Mc * Hc * 32) return;
  int j = idx & 31;
  int h = (idx >> 5) & (Hc - 1);
  int m = idx >> 9;            // 0..4095 (b*S+s)
  int s = m & (Sc - 1);
  float cs = g_cs[s * 32 + j];
  float sn = g_sn[s * 32 + j];
  size_t base = (size_t)m * DIMc + h * DHc;
  float q1 = q[base + j], q2 = q[base + j + 32];
  q[base + j]      = fmaf(q1, cs, -q2 * sn);
  q[base + j + 32] = fmaf(q2, cs,  q1 * sn);
  float k1 = k[base + j], k2 = k[base + j + 32];
  k[base + j]      = fmaf(k1, cs, -k2 * sn);
  k[base + j + 32] = fmaf(k2, cs,  k1 * sn);
}

// ----------------------------------------------------------------------------
// Flash attention fp32: 64 q-rows per block, 64-col kv tiles, online softmax.
// q,k,v,o in (B,S,H,DH) row-major layout. 256 threads = 16x16, 4x4 microtiles.
// ----------------------------------------------------------------------------
#define FPAD 68
__global__ void __launch_bounds__(256) flash_kernel(
    const float* __restrict__ q, const float* __restrict__ k,
    const float* __restrict__ v, float* __restrict__ o) {
  extern __shared__ float sm[];
  float* Qs = sm;                  // [d][i], 64 x FPAD
  float* Ks = Qs + 64 * FPAD;      // [d][j]
  float* Vs = Ks + 64 * FPAD;      // [j][d]
  float* Ps = Vs + 64 * FPAD;      // [j][i]

  const int tid = threadIdx.x;
  const int tx = tid & 15, ty = tid >> 4;
  const int bh = blockIdx.y;
  const int b = bh >> 4, h = bh & 15;
  const int q0 = blockIdx.x * 64;
  const float* qb = q + (size_t)b * Sc * DIMc + h * DHc;
  const float* kb = k + (size_t)b * Sc * DIMc + h * DHc;
  const float* vb = v + (size_t)b * Sc * DIMc + h * DHc;

  // Load Q tile, transposed into Qs[d][i]
  for (int idx = tid; idx < 64 * 16; idx += 256) {
    int i = idx >> 4, d4 = (idx & 15) * 4;
    float4 t4 = *(const float4*)(qb + (size_t)(q0 + i) * DIMc + d4);
    Qs[(d4 + 0) * FPAD + i] = t4.x;
    Qs[(d4 + 1) * FPAD + i] = t4.y;
    Qs[(d4 + 2) * FPAD + i] = t4.z;
    Qs[(d4 + 3) * FPAD + i] = t4.w;
  }

  float m_i[4], l_i[4], acc[4][4];
#pragma unroll
  for (int r = 0; r < 4; r++) {
    m_i[r] = -INFINITY;
    l_i[r] = 0.f;
#pragma unroll
    for (int c = 0; c < 4; c++) acc[r][c] = 0.f;
  }

  const float scale = 0.125f;  // 1/sqrt(64)

  for (int t = 0; t < 16; t++) {
    int kv0 = t * 64;
    __syncthreads();  // protect Ks/Vs/Ps from previous iteration readers
    for (int idx = tid; idx < 64 * 16; idx += 256) {
      int j = idx >> 4, d4 = (idx & 15) * 4;
      float4 t4 = *(const float4*)(kb + (size_t)(kv0 + j) * DIMc + d4);
      Ks[(d4 + 0) * FPAD + j] = t4.x;
      Ks[(d4 + 1) * FPAD + j] = t4.y;
      Ks[(d4 + 2) * FPAD + j] = t4.z;
      Ks[(d4 + 3) * FPAD + j] = t4.w;
      float4 v4 = *(const float4*)(vb + (size_t)(kv0 + j) * DIMc + d4);
      *(float4*)(Vs + j * FPAD + d4) = v4;
    }
    __syncthreads();

    // S = Q K^T (64x64x64)
    float s[4][4];
#pragma unroll
    for (int r = 0; r < 4; r++)
#pragma unroll
      for (int c = 0; c < 4; c++) s[r][c] = 0.f;
#pragma unroll 16
    for (int d = 0; d < 64; d++) {
      float4 a = *(const float4*)&Qs[d * FPAD + ty * 4];
      float4 bb = *(const float4*)&Ks[d * FPAD + tx * 4];
      float ar[4] = {a.x, a.y, a.z, a.w};
      float br[4] = {bb.x, bb.y, bb.z, bb.w};
#pragma unroll
      for (int r = 0; r < 4; r++)
#pragma unroll
        for (int c = 0; c < 4; c++) s[r][c] = fmaf(ar[r], br[c], s[r][c]);
    }

    // Online softmax per row; row group = 16 lanes (aligned), xor-shuffle reduce
#pragma unroll
    for (int r = 0; r < 4; r++) {
#pragma unroll
      for (int c = 0; c < 4; c++) s[r][c] *= scale;
      float mx = fmaxf(fmaxf(s[r][0], s[r][1]), fmaxf(s[r][2], s[r][3]));
#pragma unroll
      for (int off = 8; off > 0; off >>= 1)
        mx = fmaxf(mx, __shfl_xor_sync(0xffffffffu, mx, off));
      float mn = fmaxf(m_i[r], mx);
      float corr = __expf(m_i[r] - mn);
      float rs = 0.f;
#pragma unroll
      for (int c = 0; c < 4; c++) {
        float p = __expf(s[r][c] - mn);
        rs += p;
        Ps[(tx * 4 + c) * FPAD + ty * 4 + r] = p;
      }
#pragma unroll
      for (int off = 8; off > 0; off >>= 1)
        rs += __shfl_xor_sync(0xffffffffu, rs, off);
      l_i[r] = l_i[r] * corr + rs;
      m_i[r] = mn;
#pragma unroll
      for (int c = 0; c < 4; c++) acc[r][c] *= corr;
    }
    __syncthreads();

    // O += P V (64x64x64)
#pragma unroll 16
    for (int j = 0; j < 64; j++) {
      float4 a = *(const float4*)&Ps[j * FPAD + ty * 4];
      float4 bv = *(const float4*)&Vs[j * FPAD + tx * 4];
      float ar[4] = {a.x, a.y, a.z, a.w};
      float br[4] = {bv.x, bv.y, bv.z, bv.w};
#pragma unroll
      for (int r = 0; r < 4; r++)
#pragma unroll
        for (int c = 0; c < 4; c++) acc[r][c] = fmaf(ar[r], br[c], acc[r][c]);
    }
  }

  // Writeback o[b, q0+row, h, :]
#pragma unroll
  for (int r = 0; r < 4; r++) {
    float inv = 1.f / l_i[r];
    float4 ov = make_float4(acc[r][0] * inv, acc[r][1] * inv,
                            acc[r][2] * inv, acc[r][3] * inv);
    *(float4*)(o + (size_t)(b * Sc + q0 + ty * 4 + r) * DIMc + h * DHc +
               tx * 4) = ov;
  }
}

// ----------------------------------------------------------------------------
extern "C" void kernel_launch(void* const* d_in, const int* in_sizes, int n_in,
                              void* d_out, int out_size) {
  const float* x  = (const float*)d_in[0];
  const float* Wq = (const float*)d_in[1];
  const float* bq = (const float*)d_in[2];
  const float* Wk = (const float*)d_in[3];
  const float* bk = (const float*)d_in[4];
  const float* Wv = (const float*)d_in[5];
  const float* bv = (const float*)d_in[6];
  const float* Wo = (const float*)d_in[7];
  const float* bo = (const float*)d_in[8];
  float* out = (float*)d_out;

  float *qp, *kp, *vp, *op;
  cudaGetSymbolAddress((void**)&qp, g_q);
  cudaGetSymbolAddress((void**)&kp, g_k);
  cudaGetSymbolAddress((void**)&vp, g_v);
  cudaGetSymbolAddress((void**)&op, g_o);

  // RoPE table (cheap; independent of GEMMs, launch first)
  rope_table_kernel<<<(Sc * 32 + 255) / 256, 256>>>();

  dim3 gqkv(DIMc / 128, Mc / 128, 3);  // (8, 32, 3)
  sgemm_bias_qkv<<<gqkv, 256>>>(x, Wq, bq, qp, Wk, bk, kp, Wv, bv, vp, DIMc, DIMc);

  int total = Mc * Hc * 32;
  rope_apply_kernel<<<(total + 255) / 256, 256>>>(qp, kp);

  size_t shm = 4 * 64 * FPAD * sizeof(float);  // 69632 B
  cudaFuncSetAttribute(flash_kernel, cudaFuncAttributeMaxDynamicSharedMemorySize,
                       (int)shm);
  flash_kernel<<<dim3(Sc / 64, Bc * Hc), 256, shm>>>(qp, kp, vp, op);

  dim3 gg(DIMc / 128, Mc / 128);  // (8, 32)
  sgemm_bias<<<gg, 256>>>(op, Wo, bo, out, DIMc, DIMc);
}